// round 3
// baseline (speedup 1.0000x reference)
#include <cuda_runtime.h>
#include <cuda_bf16.h>

#define CLS 128
#define NCNT (5 * CLS)

// [0:128)   diag[c]   : true==pred==c           (TP)
// [128:256) colA[c]   : true=c, pred=0          (conf[c,0])
// [256:384) colB[c]   : true=c, pred=1          (conf[c,1])
// [384:512) rowA[c]   : true=0, pred=c          (conf[0,c])
// [512:640) rowB[c]   : true=1, pred=c          (conf[1,c])
__device__ int g_cnt[NCNT];

__global__ void zero_kernel() {
    int i = blockIdx.x * blockDim.x + threadIdx.x;
    if (i < NCNT) g_cnt[i] = 0;
}

__global__ void __launch_bounds__(256) conf_kernel(const float* __restrict__ y_pred,
                                                   const int* __restrict__ y_true,
                                                   int n, int tstride) {
    __shared__ int s_cnt[NCNT];
    for (int i = threadIdx.x; i < NCNT; i += blockDim.x) s_cnt[i] = 0;
    __syncthreads();

    const int lane = threadIdx.x & 31;
    const int warp = threadIdx.x >> 5;
    const long long gwarp  = (long long)blockIdx.x * (blockDim.x >> 5) + warp;
    const long long nwarps = (long long)gridDim.x * (blockDim.x >> 5);

    for (long long row = gwarp; row < n; row += nwarps) {
        // one warp per row: lane i loads float4 -> 128 floats, fully coalesced
        const float4* p = reinterpret_cast<const float4*>(y_pred + row * CLS) + lane;
        float4 v = __ldcs(p);   // streaming: zero reuse, don't pollute L2

        float bv = v.x; int bi = lane * 4;
        if (v.y > bv) { bv = v.y; bi = lane * 4 + 1; }
        if (v.z > bv) { bv = v.z; bi = lane * 4 + 2; }
        if (v.w > bv) { bv = v.w; bi = lane * 4 + 3; }

        // butterfly argmax reduce; tie -> smaller index (jnp.argmax first-occurrence)
        #pragma unroll
        for (int off = 16; off; off >>= 1) {
            float ov = __shfl_xor_sync(0xffffffffu, bv, off);
            int   oi = __shfl_xor_sync(0xffffffffu, bi, off);
            if (ov > bv || (ov == bv && oi < bi)) { bv = ov; bi = oi; }
        }

        if (lane == 0) {
            // little-endian low word holds the class id whether the buffer is
            // int32 (tstride=1) or int64 stored as 32-bit words (tstride=2)
            int t  = y_true[row * tstride];
            int pr = bi;
            if (t == pr)  atomicAdd(&s_cnt[t], 1);
            if (pr == 0)  atomicAdd(&s_cnt[CLS     + t], 1);
            if (pr == 1)  atomicAdd(&s_cnt[2 * CLS + t], 1);
            if (t == 0)   atomicAdd(&s_cnt[3 * CLS + pr], 1);
            if (t == 1)   atomicAdd(&s_cnt[4 * CLS + pr], 1);
        }
    }
    __syncthreads();
    for (int i = threadIdx.x; i < NCNT; i += blockDim.x) {
        int v = s_cnt[i];
        if (v) atomicAdd(&g_cnt[i], v);
    }
}

__global__ void finalize_kernel(float* __restrict__ out) {
    __shared__ float s[CLS];
    const int c = threadIdx.x;   // 128 threads
    const float eps = 1e-12f;

    float TP = (float)g_cnt[c];
    float FP = 127.0f * (float)g_cnt[2 * CLS + c] + (float)g_cnt[CLS + c];
    float FN = 127.0f * (float)g_cnt[4 * CLS + c] + (float)g_cnt[3 * CLS + c];

    float sens = TP / (TP + FN + eps);
    float prec = TP / (TP + FP + eps);
    float f1   = 2.0f * (prec * sens / (prec + sens + eps));
    s[c] = f1;
    __syncthreads();

    #pragma unroll
    for (int off = 64; off; off >>= 1) {
        if (c < off) s[c] += s[c + off];
        __syncthreads();
    }
    if (c == 0) out[0] = s[0] / (float)CLS;
}

extern "C" void kernel_launch(void* const* d_in, const int* in_sizes, int n_in,
                              void* d_out, int out_size) {
    const float* y_pred = (const float*)d_in[0];
    const int*   y_true = (const int*)d_in[1];

    int n = in_sizes[0] / CLS;            // rows, derived from y_pred (unambiguous)
    int tstride = in_sizes[1] / n;        // 1 if int32, 2 if int64 passed as words
    if (tstride < 1) tstride = 1;

    zero_kernel<<<(NCNT + 255) / 256, 256>>>();
    conf_kernel<<<2048, 256>>>(y_pred, y_true, n, tstride);
    finalize_kernel<<<1, CLS>>>((float*)d_out);
}

// round 4
// speedup vs baseline: 1.6385x; 1.6385x over previous
#include <cuda_runtime.h>
#include <cuda_bf16.h>

#define CLS 128
#define NCNT (5 * CLS)
#define ILP 4

// [0:128)   diag[c]   : true==pred==c           (TP)
// [128:256) colA[c]   : true=c, pred=0          (conf[c,0])
// [256:384) colB[c]   : true=c, pred=1          (conf[c,1])
// [384:512) rowA[c]   : true=0, pred=c          (conf[0,c])
// [512:640) rowB[c]   : true=1, pred=c          (conf[1,c])
__device__ int g_cnt[NCNT];

__global__ void zero_kernel() {
    int i = blockIdx.x * blockDim.x + threadIdx.x;
    if (i < NCNT) g_cnt[i] = 0;
}

__device__ __forceinline__ unsigned f2key(float f) {
    unsigned u = __float_as_uint(f);
    return (u & 0x80000000u) ? ~u : (u | 0x80000000u);  // monotone: key order == float order
}

__global__ void __launch_bounds__(256) conf_kernel(const float* __restrict__ y_pred,
                                                   const int* __restrict__ y_true,
                                                   int n, int tstride) {
    __shared__ int s_cnt[NCNT];
    for (int i = threadIdx.x; i < NCNT; i += blockDim.x) s_cnt[i] = 0;
    __syncthreads();

    const int lane = threadIdx.x & 31;
    const int warp = threadIdx.x >> 5;
    const long long gwarp  = (long long)blockIdx.x * (blockDim.x >> 5) + warp;
    const long long nwarps = (long long)gridDim.x * (blockDim.x >> 5);

    for (long long r0 = gwarp * ILP; r0 < n; r0 += nwarps * ILP) {
        // Front-batched loads: 4 rows x 512B contiguous -> MLP=4 per warp
        float4 v[ILP];
        #pragma unroll
        for (int k = 0; k < ILP; k++) {
            long long r = r0 + k;
            if (r < n)
                v[k] = __ldcs(reinterpret_cast<const float4*>(y_pred + r * CLS) + lane);
            else
                v[k] = make_float4(0.f, 0.f, 0.f, 0.f);
        }

        int pr[ILP];
        #pragma unroll
        for (int k = 0; k < ILP; k++) {
            float bv = v[k].x; int bi = lane * 4;
            if (v[k].y > bv) { bv = v[k].y; bi = lane * 4 + 1; }
            if (v[k].z > bv) { bv = v[k].z; bi = lane * 4 + 2; }
            if (v[k].w > bv) { bv = v[k].w; bi = lane * 4 + 3; }
            // warp argmax: REDUX on monotone key, lowest winning lane = first occurrence
            unsigned key = f2key(bv);
            unsigned m   = __reduce_max_sync(0xffffffffu, key);
            unsigned bal = __ballot_sync(0xffffffffu, key == m);
            pr[k] = __shfl_sync(0xffffffffu, bi, __ffs(bal) - 1);
        }

        if (lane < ILP) {
            long long r = r0 + lane;
            if (r < n) {
                int t = y_true[r * tstride];   // low word = class id for int32 or LE int64
                int p = pr[lane];
                if (t == p)  atomicAdd(&s_cnt[t], 1);
                if (p == 0)  atomicAdd(&s_cnt[CLS     + t], 1);
                if (p == 1)  atomicAdd(&s_cnt[2 * CLS + t], 1);
                if (t == 0)  atomicAdd(&s_cnt[3 * CLS + p], 1);
                if (t == 1)  atomicAdd(&s_cnt[4 * CLS + p], 1);
            }
        }
    }
    __syncthreads();
    for (int i = threadIdx.x; i < NCNT; i += blockDim.x) {
        int c = s_cnt[i];
        if (c) atomicAdd(&g_cnt[i], c);
    }
}

__global__ void finalize_kernel(float* __restrict__ out) {
    __shared__ float s[CLS];
    const int c = threadIdx.x;   // 128 threads
    const float eps = 1e-12f;

    float TP = (float)g_cnt[c];
    float FP = 127.0f * (float)g_cnt[2 * CLS + c] + (float)g_cnt[CLS + c];
    float FN = 127.0f * (float)g_cnt[4 * CLS + c] + (float)g_cnt[3 * CLS + c];

    float sens = TP / (TP + FN + eps);
    float prec = TP / (TP + FP + eps);
    float f1   = 2.0f * (prec * sens / (prec + sens + eps));
    s[c] = f1;
    __syncthreads();

    #pragma unroll
    for (int off = 64; off; off >>= 1) {
        if (c < off) s[c] += s[c + off];
        __syncthreads();
    }
    if (c == 0) out[0] = s[0] / (float)CLS;
}

extern "C" void kernel_launch(void* const* d_in, const int* in_sizes, int n_in,
                              void* d_out, int out_size) {
    const float* y_pred = (const float*)d_in[0];
    const int*   y_true = (const int*)d_in[1];

    int n = in_sizes[0] / CLS;            // rows, derived from y_pred (unambiguous)
    int tstride = in_sizes[1] / n;        // 1 if int32, 2 if int64 passed as words
    if (tstride < 1) tstride = 1;

    zero_kernel<<<(NCNT + 255) / 256, 256>>>();
    conf_kernel<<<2048, 256>>>(y_pred, y_true, n, tstride);
    finalize_kernel<<<1, CLS>>>((float*)d_out);
}